// round 7
// baseline (speedup 1.0000x reference)
#include <cuda_runtime.h>
#include <cuda_fp16.h>
#include <cstdint>

// Problem constants (fixed by the dataset)
#define T_TOK 16384
#define DDIM  1024
#define NEXP  8

// GEMM tiling: CTA 256x128, warp 64x64 (8 warps: 4 rows x 2 cols)
#define MT  256
#define NT  128
#define KC  64
#define NCH (DDIM / KC)          // 16 k-chunks
#define NSTAGE 3
#define A_STG 32768              // 256 rows x 64 k x 2B
#define B_STG 16384              // 128 rows x 64 k x 2B
#define STAGE_B (A_STG + B_STG)  // 49152
#define SMEM_DYN (NSTAGE * STAGE_B)  // 147456
#define MAX_TILES 136            // sum ceil(cnt_e/256) <= 128 + 8

// ---------------------------------------------------------------------------
// Scratch (device globals; allocation is forbidden)
// ---------------------------------------------------------------------------
__device__ int    g_count[NEXP];
__device__ int    g_tok [NEXP][T_TOK];
__device__ float  g_gate[NEXP][T_TOK];
__device__ float  g_logits[(size_t)T_TOK * NEXP];
__device__ int    g_tile_e[MAX_TILES];
__device__ int    g_tile_m0[MAX_TILES];
__device__ __half g_xf[(size_t)T_TOK * DDIM];             // x in fp16
__device__ __half g_wf[(size_t)NEXP * DDIM * DDIM];       // We in fp16

// ---------------------------------------------------------------------------
// PTX helpers (base-ISA only: plain sm_103 target)
// ---------------------------------------------------------------------------
__device__ __forceinline__ uint32_t smem_u32(const void* p) {
    uint32_t a;
    asm("{ .reg .u64 t; cvta.to.shared.u64 t, %1; cvt.u32.u64 %0, t; }" : "=r"(a) : "l"(p));
    return a;
}
__device__ __forceinline__ uint32_t swz(uint32_t o) { return o ^ ((o >> 3) & 0x70); }

__device__ __forceinline__ void cp16(uint32_t dst, const void* src) {
    asm volatile("cp.async.cg.shared.global [%0], [%1], 16;" :: "r"(dst), "l"(src));
}
#define CP_COMMIT() asm volatile("cp.async.commit_group;" ::: "memory")
#define CP_WAIT(n)  asm volatile("cp.async.wait_group %0;" :: "n"(n) : "memory")

__device__ __forceinline__ void ldmx4(uint32_t* r, uint32_t addr) {
    asm volatile("ldmatrix.sync.aligned.m8n8.x4.shared.b16 {%0,%1,%2,%3}, [%4];"
                 : "=r"(r[0]), "=r"(r[1]), "=r"(r[2]), "=r"(r[3]) : "r"(addr));
}

__device__ __forceinline__ void mma16816(float* c, const uint32_t* a, const uint32_t* b) {
    asm volatile("mma.sync.aligned.m16n8k16.row.col.f32.f16.f16.f32 "
                 "{%0,%1,%2,%3}, {%4,%5,%6,%7}, {%8,%9}, {%0,%1,%2,%3};"
                 : "+f"(c[0]), "+f"(c[1]), "+f"(c[2]), "+f"(c[3])
                 : "r"(a[0]), "r"(a[1]), "r"(a[2]), "r"(a[3]), "r"(b[0]), "r"(b[1]));
}

__device__ __forceinline__ void red_v2(float* p, float v0, float v1) {
    asm volatile("red.global.add.v2.f32 [%0], {%1, %2};" :: "l"(p), "f"(v0), "f"(v1) : "memory");
}

// ---------------------------------------------------------------------------
// Kernel 0: fused zero(out) + counter reset + We fp32->fp16 (one HBM pass)
// grid = 16384 + 8192 blocks x 256 threads
// ---------------------------------------------------------------------------
__global__ void prep_kernel(float* __restrict__ out, const float* __restrict__ w) {
    const int b = blockIdx.x;
    const int tid = threadIdx.x;
    if (b < 16384) {
        int i = b * 256 + tid;
        reinterpret_cast<float4*>(out)[i] = make_float4(0.f, 0.f, 0.f, 0.f);
        if (b == 0 && tid < NEXP) g_count[tid] = 0;
    } else {
        int i = (b - 16384) * 256 + tid;
        float4 v = reinterpret_cast<const float4*>(w)[i];
        __half2* d = reinterpret_cast<__half2*>(g_wf);
        d[i * 2 + 0] = __floats2half2_rn(v.x, v.y);
        d[i * 2 + 1] = __floats2half2_rn(v.z, v.w);
    }
}

// ---------------------------------------------------------------------------
// Kernel 1: fused x fp32->fp16 convert + gate logits.
// One block = one token row (1024 elems, 256 threads x float4).
// ---------------------------------------------------------------------------
__global__ void __launch_bounds__(256)
cvt_x_gate_kernel(const float* __restrict__ x,
                  const float* __restrict__ Wg,
                  const float* __restrict__ bg) {
    const int t = blockIdx.x;
    const int i = threadIdx.x;

    float4 v = reinterpret_cast<const float4*>(x + (size_t)t * DDIM)[i];

    __half2* d = reinterpret_cast<__half2*>(g_xf + (size_t)t * DDIM);
    d[i * 2 + 0] = __floats2half2_rn(v.x, v.y);
    d[i * 2 + 1] = __floats2half2_rn(v.z, v.w);

    float acc[NEXP];
#pragma unroll
    for (int e = 0; e < NEXP; e++) {
        float4 w = reinterpret_cast<const float4*>(Wg + e * DDIM)[i];
        acc[e] = v.x * w.x + v.y * w.y + v.z * w.z + v.w * w.w;
    }
#pragma unroll
    for (int off = 16; off > 0; off >>= 1)
#pragma unroll
        for (int e = 0; e < NEXP; e++)
            acc[e] += __shfl_xor_sync(0xFFFFFFFFu, acc[e], off);

    __shared__ float red[8][NEXP];
    const int warp = i >> 5, lane = i & 31;
    if (lane == 0)
#pragma unroll
        for (int e = 0; e < NEXP; e++) red[warp][e] = acc[e];
    __syncthreads();

    if (i < NEXP) {
        float s = bg[i];
#pragma unroll
        for (int w = 0; w < 8; w++) s += red[w][i];
        g_logits[(size_t)t * NEXP + i] = s;
    }
}

// ---------------------------------------------------------------------------
// Kernel 2: top-2 + softmax + block-aggregated compaction.
// ---------------------------------------------------------------------------
__global__ void __launch_bounds__(256)
topk_kernel() {
    const int tid = threadIdx.x;
    const int t = blockIdx.x * 256 + tid;

    __shared__ int cnt_s[NEXP];
    __shared__ int base_s[NEXP];
    if (tid < NEXP) cnt_s[tid] = 0;
    __syncthreads();

    float l[NEXP];
    float4 l0 = reinterpret_cast<const float4*>(g_logits + (size_t)t * NEXP)[0];
    float4 l1 = reinterpret_cast<const float4*>(g_logits + (size_t)t * NEXP)[1];
    l[0]=l0.x; l[1]=l0.y; l[2]=l0.z; l[3]=l0.w;
    l[4]=l1.x; l[5]=l1.y; l[6]=l1.z; l[7]=l1.w;

    int i0 = 0;
#pragma unroll
    for (int e = 1; e < NEXP; e++) if (l[e] > l[i0]) i0 = e;
    int i1 = (i0 == 0) ? 1 : 0;
#pragma unroll
    for (int e = 0; e < NEXP; e++) {
        if (e == i0) continue;
        if (l[e] > l[i1]) i1 = e;
    }
    float m  = fmaxf(l[i0], l[i1]);
    float e0 = __expf(l[i0] - m);
    float e1 = __expf(l[i1] - m);
    float inv = 1.f / (e0 + e1);

    int p0 = atomicAdd(&cnt_s[i0], 1);
    int p1 = atomicAdd(&cnt_s[i1], 1);
    __syncthreads();
    if (tid < NEXP) base_s[tid] = atomicAdd(&g_count[tid], cnt_s[tid]);
    __syncthreads();

    int q0 = base_s[i0] + p0;
    g_tok[i0][q0] = t; g_gate[i0][q0] = e0 * inv;
    int q1 = base_s[i1] + p1;
    g_tok[i1][q1] = t; g_gate[i1][q1] = e1 * inv;
}

// ---------------------------------------------------------------------------
// Kernel 2b: build active tile list (expert, m0) pairs; pad with e=-1.
// ---------------------------------------------------------------------------
__global__ void tile_map_kernel() {
    __shared__ int base[NEXP + 1];
    if (threadIdx.x == 0) {
        int s = 0;
        for (int e = 0; e < NEXP; e++) {
            base[e] = s;
            s += (g_count[e] + MT - 1) / MT;
        }
        base[NEXP] = s;
    }
    __syncthreads();
    int i = threadIdx.x;
    if (i < MAX_TILES) {
        int e = -1;
#pragma unroll
        for (int q = 0; q < NEXP; q++)
            if (i >= base[q] && i < base[q + 1]) e = q;
        g_tile_e[i]  = e;
        g_tile_m0[i] = (e >= 0) ? (i - base[e]) * MT : 0;
    }
}

// ---------------------------------------------------------------------------
// Kernel 3: fp16 HMMA expert GEMM, CTA 256x128, warp 64x64, 3-stage cp.async.
// Grid (8 n-tiles, MAX_TILES). Epilogue via red.global.add.v2.f32.
// ---------------------------------------------------------------------------
__global__ void __launch_bounds__(256, 1)
moe_gemm_kernel(const float* __restrict__ be, float* __restrict__ out) {
    const int e = g_tile_e[blockIdx.y];
    if (e < 0) return;
    const int m0  = g_tile_m0[blockIdx.y];
    const int cnt = g_count[e];
    const int n0  = blockIdx.x * NT;

    extern __shared__ __align__(128) char smem[];
    const uint32_t sbase = smem_u32(smem);

    __shared__ int   s_tok[MT];
    __shared__ float s_gate[MT];

    const int tid  = threadIdx.x;
    const int wid  = tid >> 5, lane = tid & 31;
    const int wm   = (wid & 3) * 64;     // warp row offset (4 warp-rows)
    const int wn   = (wid >> 2) * 64;    // warp col offset (2 warp-cols)

    {
        int m = m0 + tid;
        s_tok[tid]  = (m < cnt) ? g_tok[e][m]  : 0;
        s_gate[tid] = (m < cnt) ? g_gate[e][m] : 0.f;
    }
    __syncthreads();

    const size_t wbase = ((size_t)e << 20) + (size_t)n0 * DDIM;  // e*1024*1024

    auto load_stage = [&](int ck, int s) {
        const int k0 = ck * KC;
        const uint32_t sA = sbase + s * STAGE_B;
        const uint32_t sB = sA + A_STG;
#pragma unroll
        for (int i = 0; i < 8; i++) {                 // A: 256 rows x 8 16B-chunks
            int u = tid + i * 256;
            int row = u >> 3, c = u & 7;
            const __half* src = &g_xf[(size_t)s_tok[row] * DDIM + k0 + c * 8];
            cp16(sA + swz((uint32_t)(row * 128 + c * 16)), src);
        }
#pragma unroll
        for (int i = 0; i < 4; i++) {                 // B: 128 rows x 8 16B-chunks
            int u = tid + i * 256;
            int row = u >> 3, c = u & 7;
            const __half* src = &g_wf[wbase + (size_t)row * DDIM + k0 + c * 8];
            cp16(sB + swz((uint32_t)(row * 128 + c * 16)), src);
        }
        CP_COMMIT();
    };

    float acc[4][8][4];
#pragma unroll
    for (int mi = 0; mi < 4; mi++)
#pragma unroll
        for (int ni = 0; ni < 8; ni++)
#pragma unroll
            for (int q = 0; q < 4; q++) acc[mi][ni][q] = 0.f;

    load_stage(0, 0);
    load_stage(1, 1);

#pragma unroll 1
    for (int ck = 0; ck < NCH; ck++) {
        if (ck + 1 < NCH) { CP_WAIT(1); } else { CP_WAIT(0); }
        __syncthreads();
        // Slot (ck+2)%3 finished its MMAs at iteration ck-1 (barrier above).
        if (ck + 2 < NCH) load_stage(ck + 2, (ck + 2) % NSTAGE);

        const uint32_t sA = sbase + (ck % NSTAGE) * STAGE_B;
        const uint32_t sB = sA + A_STG;

#pragma unroll
        for (int ks = 0; ks < 4; ks++) {
            uint32_t a[4][4];
#pragma unroll
            for (int mi = 0; mi < 4; mi++) {
                int row = wm + mi * 16 + (lane & 15);
                ldmx4(a[mi], sA + swz((uint32_t)(row * 128 + (ks * 2 + (lane >> 4)) * 16)));
            }
            uint32_t b[4][4];
#pragma unroll
            for (int pi = 0; pi < 4; pi++) {
                int n = wn + pi * 16 + ((lane >> 4) << 3) + (lane & 7);
                ldmx4(b[pi], sB + swz((uint32_t)(n * 128 + (ks * 2 + ((lane >> 3) & 1)) * 16)));
            }
#pragma unroll
            for (int mi = 0; mi < 4; mi++)
#pragma unroll
                for (int ni = 0; ni < 8; ni++)
                    mma16816(acc[mi][ni], a[mi], &b[ni >> 1][(ni & 1) * 2]);
        }
    }

    // --- epilogue ---
    const float* brow = be + (size_t)e * DDIM + n0 + wn;
    float2 bias[8];
#pragma unroll
    for (int ni = 0; ni < 8; ni++)
        bias[ni] = *reinterpret_cast<const float2*>(brow + ni * 8 + 2 * (lane & 3));

#pragma unroll
    for (int mi = 0; mi < 4; mi++)
#pragma unroll
        for (int h = 0; h < 2; h++) {
            int mrow = wm + mi * 16 + (lane >> 2) + h * 8;
            if (m0 + mrow < cnt) {
                int tok = s_tok[mrow];
                float g = s_gate[mrow];
                float* orow = out + (size_t)tok * DDIM + n0 + wn + 2 * (lane & 3);
#pragma unroll
                for (int ni = 0; ni < 8; ni++) {
                    red_v2(orow + ni * 8,
                           g * (acc[mi][ni][h * 2 + 0] + bias[ni].x),
                           g * (acc[mi][ni][h * 2 + 1] + bias[ni].y));
                }
            }
        }
}

// ---------------------------------------------------------------------------
extern "C" void kernel_launch(void* const* d_in, const int* in_sizes, int n_in,
                              void* d_out, int out_size) {
    const float* x  = (const float*)d_in[0];   // [16384, 1024]
    const float* Wg = (const float*)d_in[1];   // [8, 1024]
    const float* bg = (const float*)d_in[2];   // [8]
    const float* We = (const float*)d_in[3];   // [8, 1024, 1024]
    const float* be = (const float*)d_in[4];   // [8, 1024]
    float* out = (float*)d_out;                // [16384, 1024]

    cudaFuncSetAttribute(moe_gemm_kernel,
                         cudaFuncAttributeMaxDynamicSharedMemorySize, SMEM_DYN);

    prep_kernel<<<16384 + 8192, 256>>>(out, We);
    cvt_x_gate_kernel<<<T_TOK, 256>>>(x, Wg, bg);
    topk_kernel<<<T_TOK / 256, 256>>>();
    tile_map_kernel<<<1, 256>>>();

    dim3 grid(DDIM / NT, MAX_TILES);   // (8, 136)
    moe_gemm_kernel<<<grid, 256, SMEM_DYN>>>(be, out);
}

// round 8
// speedup vs baseline: 1.1038x; 1.1038x over previous
#include <cuda_runtime.h>
#include <cuda_fp16.h>
#include <cstdint>

// Problem constants (fixed by the dataset)
#define T_TOK 16384
#define DDIM  1024
#define NEXP  8

// GEMM tiling: CTA 128x128, warp 32x64 (8 warps: 4 rows x 2 cols)
#define MT  128
#define NT  128
#define KC  64
#define NCH (DDIM / KC)          // 16 k-chunks
#define NSTAGE 3
#define STAGE_B 32768            // A(16KB) + B(16KB) per stage
#define SMEM_DYN (NSTAGE * STAGE_B)  // 96KB -> 2 CTAs/SM
#define MAX_TILES 264            // sum ceil(cnt_e/128) <= 256 + 8

// ---------------------------------------------------------------------------
// Scratch (device globals; allocation is forbidden)
// ---------------------------------------------------------------------------
__device__ int    g_count[NEXP];
__device__ int    g_tok [NEXP][T_TOK];
__device__ float  g_gate[NEXP][T_TOK];
__device__ float  g_logits[(size_t)T_TOK * NEXP];
__device__ __half g_xf[(size_t)T_TOK * DDIM];             // x in fp16
__device__ __half g_wf[(size_t)NEXP * DDIM * DDIM];       // We in fp16

// ---------------------------------------------------------------------------
// PTX helpers (base-ISA only: plain sm_103 target)
// ---------------------------------------------------------------------------
__device__ __forceinline__ uint32_t smem_u32(const void* p) {
    uint32_t a;
    asm("{ .reg .u64 t; cvta.to.shared.u64 t, %1; cvt.u32.u64 %0, t; }" : "=r"(a) : "l"(p));
    return a;
}
__device__ __forceinline__ uint32_t swz(uint32_t o) { return o ^ ((o >> 3) & 0x70); }

__device__ __forceinline__ void cp16(uint32_t dst, const void* src) {
    asm volatile("cp.async.cg.shared.global [%0], [%1], 16;" :: "r"(dst), "l"(src));
}
#define CP_COMMIT() asm volatile("cp.async.commit_group;" ::: "memory")
#define CP_WAIT(n)  asm volatile("cp.async.wait_group %0;" :: "n"(n) : "memory")

__device__ __forceinline__ void ldmx4(uint32_t* r, uint32_t addr) {
    asm volatile("ldmatrix.sync.aligned.m8n8.x4.shared.b16 {%0,%1,%2,%3}, [%4];"
                 : "=r"(r[0]), "=r"(r[1]), "=r"(r[2]), "=r"(r[3]) : "r"(addr));
}

__device__ __forceinline__ void mma16816(float* c, const uint32_t* a, const uint32_t* b) {
    asm volatile("mma.sync.aligned.m16n8k16.row.col.f32.f16.f16.f32 "
                 "{%0,%1,%2,%3}, {%4,%5,%6,%7}, {%8,%9}, {%0,%1,%2,%3};"
                 : "+f"(c[0]), "+f"(c[1]), "+f"(c[2]), "+f"(c[3])
                 : "r"(a[0]), "r"(a[1]), "r"(a[2]), "r"(a[3]), "r"(b[0]), "r"(b[1]));
}

__device__ __forceinline__ void red_v2(float* p, float v0, float v1) {
    asm volatile("red.global.add.v2.f32 [%0], {%1, %2};" :: "l"(p), "f"(v0), "f"(v1) : "memory");
}

// ---------------------------------------------------------------------------
// Kernel 0: fused zero(out) + counter reset + We fp32->fp16 (one HBM pass)
// ---------------------------------------------------------------------------
__global__ void prep_kernel(float* __restrict__ out, const float* __restrict__ w) {
    const int b = blockIdx.x;
    const int tid = threadIdx.x;
    if (b < 16384) {
        int i = b * 256 + tid;
        reinterpret_cast<float4*>(out)[i] = make_float4(0.f, 0.f, 0.f, 0.f);
        if (b == 0 && tid < NEXP) g_count[tid] = 0;
    } else {
        int i = (b - 16384) * 256 + tid;
        float4 v = reinterpret_cast<const float4*>(w)[i];
        __half2* d = reinterpret_cast<__half2*>(g_wf);
        d[i * 2 + 0] = __floats2half2_rn(v.x, v.y);
        d[i * 2 + 1] = __floats2half2_rn(v.z, v.w);
    }
}

// ---------------------------------------------------------------------------
// Kernel 1: fused x fp32->fp16 convert + gate logits. One block = one token.
// ---------------------------------------------------------------------------
__global__ void __launch_bounds__(256)
cvt_x_gate_kernel(const float* __restrict__ x,
                  const float* __restrict__ Wg,
                  const float* __restrict__ bg) {
    const int t = blockIdx.x;
    const int i = threadIdx.x;

    float4 v = reinterpret_cast<const float4*>(x + (size_t)t * DDIM)[i];

    __half2* d = reinterpret_cast<__half2*>(g_xf + (size_t)t * DDIM);
    d[i * 2 + 0] = __floats2half2_rn(v.x, v.y);
    d[i * 2 + 1] = __floats2half2_rn(v.z, v.w);

    float acc[NEXP];
#pragma unroll
    for (int e = 0; e < NEXP; e++) {
        float4 w = reinterpret_cast<const float4*>(Wg + e * DDIM)[i];
        acc[e] = v.x * w.x + v.y * w.y + v.z * w.z + v.w * w.w;
    }
#pragma unroll
    for (int off = 16; off > 0; off >>= 1)
#pragma unroll
        for (int e = 0; e < NEXP; e++)
            acc[e] += __shfl_xor_sync(0xFFFFFFFFu, acc[e], off);

    __shared__ float red[8][NEXP];
    const int warp = i >> 5, lane = i & 31;
    if (lane == 0)
#pragma unroll
        for (int e = 0; e < NEXP; e++) red[warp][e] = acc[e];
    __syncthreads();

    if (i < NEXP) {
        float s = bg[i];
#pragma unroll
        for (int w = 0; w < 8; w++) s += red[w][i];
        g_logits[(size_t)t * NEXP + i] = s;
    }
}

// ---------------------------------------------------------------------------
// Kernel 2: top-2 + softmax + block-aggregated compaction.
// ---------------------------------------------------------------------------
__global__ void __launch_bounds__(256)
topk_kernel() {
    const int tid = threadIdx.x;
    const int t = blockIdx.x * 256 + tid;

    __shared__ int cnt_s[NEXP];
    __shared__ int base_s[NEXP];
    if (tid < NEXP) cnt_s[tid] = 0;
    __syncthreads();

    float l[NEXP];
    float4 l0 = reinterpret_cast<const float4*>(g_logits + (size_t)t * NEXP)[0];
    float4 l1 = reinterpret_cast<const float4*>(g_logits + (size_t)t * NEXP)[1];
    l[0]=l0.x; l[1]=l0.y; l[2]=l0.z; l[3]=l0.w;
    l[4]=l1.x; l[5]=l1.y; l[6]=l1.z; l[7]=l1.w;

    int i0 = 0;
#pragma unroll
    for (int e = 1; e < NEXP; e++) if (l[e] > l[i0]) i0 = e;
    int i1 = (i0 == 0) ? 1 : 0;
#pragma unroll
    for (int e = 0; e < NEXP; e++) {
        if (e == i0) continue;
        if (l[e] > l[i1]) i1 = e;
    }
    float m  = fmaxf(l[i0], l[i1]);
    float e0 = __expf(l[i0] - m);
    float e1 = __expf(l[i1] - m);
    float inv = 1.f / (e0 + e1);

    int p0 = atomicAdd(&cnt_s[i0], 1);
    int p1 = atomicAdd(&cnt_s[i1], 1);
    __syncthreads();
    if (tid < NEXP) base_s[tid] = atomicAdd(&g_count[tid], cnt_s[tid]);
    __syncthreads();

    int q0 = base_s[i0] + p0;
    g_tok[i0][q0] = t; g_gate[i0][q0] = e0 * inv;
    int q1 = base_s[i1] + p1;
    g_tok[i1][q1] = t; g_gate[i1][q1] = e1 * inv;
}

// ---------------------------------------------------------------------------
// Kernel 3: fp16 HMMA expert GEMM, CTA 128x128, warp 32x64, 3-stage cp.async,
// 2 CTAs/SM. Tile list resolved inline from g_count (no map kernel, no
// no-op m-tiles). Epilogue via red.global.add.v2.f32.
// ---------------------------------------------------------------------------
__global__ void __launch_bounds__(256, 2)
moe_gemm_kernel(const float* __restrict__ be, float* __restrict__ out) {
    // inline tile map: blockIdx.y -> (expert e, row offset m0)
    int e = -1, m0 = 0;
    {
        int ty = blockIdx.y, s = 0;
#pragma unroll
        for (int q = 0; q < NEXP; q++) {
            int nt = (g_count[q] + MT - 1) / MT;
            if (e < 0 && ty < s + nt) { e = q; m0 = (ty - s) * MT; }
            s += nt;
        }
    }
    if (e < 0) return;
    const int cnt = g_count[e];
    const int n0  = blockIdx.x * NT;

    extern __shared__ __align__(128) char smem[];
    const uint32_t sbase = smem_u32(smem);

    __shared__ int   s_tok[MT];
    __shared__ float s_gate[MT];

    const int tid  = threadIdx.x;
    const int wid  = tid >> 5, lane = tid & 31;
    const int wm   = (wid & 3) * 32;     // warp row offset in tile
    const int wn   = (wid >> 2) * 64;    // warp col offset in tile

    if (tid < MT) {
        int m = m0 + tid;
        s_tok[tid]  = (m < cnt) ? g_tok[e][m]  : 0;
        s_gate[tid] = (m < cnt) ? g_gate[e][m] : 0.f;
    }
    __syncthreads();

    const size_t wbase = ((size_t)e << 20) + (size_t)n0 * DDIM;  // e*1024*1024

    auto load_stage = [&](int ck, int s) {
        const int k0 = ck * KC;
        const uint32_t sA = sbase + s * STAGE_B;
        const uint32_t sB = sA + 16384;
#pragma unroll
        for (int i = 0; i < 4; i++) {
            int u = tid + i * 256;               // 0..1023
            int row = u >> 3, c = u & 7;         // 128 rows x 8 16B-chunks
            const __half* src = &g_xf[(size_t)s_tok[row] * DDIM + k0 + c * 8];
            cp16(sA + swz((uint32_t)(row * 128 + c * 16)), src);
        }
#pragma unroll
        for (int i = 0; i < 4; i++) {
            int u = tid + i * 256;
            int row = u >> 3, c = u & 7;
            const __half* src = &g_wf[wbase + (size_t)row * DDIM + k0 + c * 8];
            cp16(sB + swz((uint32_t)(row * 128 + c * 16)), src);
        }
        CP_COMMIT();
    };

    float acc[2][8][4];
#pragma unroll
    for (int mi = 0; mi < 2; mi++)
#pragma unroll
        for (int ni = 0; ni < 8; ni++)
#pragma unroll
            for (int q = 0; q < 4; q++) acc[mi][ni][q] = 0.f;

    load_stage(0, 0);
    load_stage(1, 1);

#pragma unroll 1
    for (int ck = 0; ck < NCH; ck++) {
        if (ck + 1 < NCH) { CP_WAIT(1); } else { CP_WAIT(0); }
        __syncthreads();
        // Slot (ck+2)%3 finished its MMAs at iteration ck-1 (barrier above).
        if (ck + 2 < NCH) load_stage(ck + 2, (ck + 2) % NSTAGE);

        const uint32_t sA = sbase + (ck % NSTAGE) * STAGE_B;
        const uint32_t sB = sA + 16384;

#pragma unroll
        for (int ks = 0; ks < 4; ks++) {
            uint32_t a[2][4];
#pragma unroll
            for (int mi = 0; mi < 2; mi++) {
                int row = wm + mi * 16 + (lane & 15);
                ldmx4(a[mi], sA + swz((uint32_t)(row * 128 + (ks * 2 + (lane >> 4)) * 16)));
            }
            uint32_t b[4][4];
#pragma unroll
            for (int pi = 0; pi < 4; pi++) {
                int n = wn + pi * 16 + ((lane >> 4) << 3) + (lane & 7);
                ldmx4(b[pi], sB + swz((uint32_t)(n * 128 + (ks * 2 + ((lane >> 3) & 1)) * 16)));
            }
#pragma unroll
            for (int mi = 0; mi < 2; mi++)
#pragma unroll
                for (int ni = 0; ni < 8; ni++)
                    mma16816(acc[mi][ni], a[mi], &b[ni >> 1][(ni & 1) * 2]);
        }
    }

    // --- epilogue ---
    const float* brow = be + (size_t)e * DDIM + n0 + wn;
    float2 bias[8];
#pragma unroll
    for (int ni = 0; ni < 8; ni++)
        bias[ni] = *reinterpret_cast<const float2*>(brow + ni * 8 + 2 * (lane & 3));

#pragma unroll
    for (int mi = 0; mi < 2; mi++)
#pragma unroll
        for (int h = 0; h < 2; h++) {
            int mrow = wm + mi * 16 + (lane >> 2) + h * 8;
            if (m0 + mrow < cnt) {
                int tok = s_tok[mrow];
                float g = s_gate[mrow];
                float* orow = out + (size_t)tok * DDIM + n0 + wn + 2 * (lane & 3);
#pragma unroll
                for (int ni = 0; ni < 8; ni++) {
                    red_v2(orow + ni * 8,
                           g * (acc[mi][ni][h * 2 + 0] + bias[ni].x),
                           g * (acc[mi][ni][h * 2 + 1] + bias[ni].y));
                }
            }
        }
}

// ---------------------------------------------------------------------------
extern "C" void kernel_launch(void* const* d_in, const int* in_sizes, int n_in,
                              void* d_out, int out_size) {
    const float* x  = (const float*)d_in[0];   // [16384, 1024]
    const float* Wg = (const float*)d_in[1];   // [8, 1024]
    const float* bg = (const float*)d_in[2];   // [8]
    const float* We = (const float*)d_in[3];   // [8, 1024, 1024]
    const float* be = (const float*)d_in[4];   // [8, 1024]
    float* out = (float*)d_out;                // [16384, 1024]

    cudaFuncSetAttribute(moe_gemm_kernel,
                         cudaFuncAttributeMaxDynamicSharedMemorySize, SMEM_DYN);

    prep_kernel<<<16384 + 8192, 256>>>(out, We);
    cvt_x_gate_kernel<<<T_TOK, 256>>>(x, Wg, bg);
    topk_kernel<<<T_TOK / 256, 256>>>();

    dim3 grid(DDIM / NT, MAX_TILES);   // (8, 264)
    moe_gemm_kernel<<<grid, 256, SMEM_DYN>>>(be, out);
}